// round 12
// baseline (speedup 1.0000x reference)
#include <cuda_runtime.h>
#include <cuda_fp16.h>
#include <cstdint>

typedef uint32_t u32;

// ====================== problem constants ======================
constexpr int T_LEN = 4000;
constexpr int NT    = 413;
constexpr int NE    = 412;
constexpr int OFF   = 206;
constexpr int S_LEN = T_LEN + NT;       // 4413 valid xe samples
constexpr int NROWS = 4096;

constexpr int KC     = 64;
constexpr int NCHUNK = 9;               // R10 structure: per-wn dead chunk skipped
constexpr int MT     = 128;             // rows per CTA
constexpr int NTT    = 128;             // t per CTA
constexpr int N_TTILE = (T_LEN + NTT - 1) / NTT;  // 32
constexpr int N_RBLK  = NROWS / MT;               // 32
constexpr int THREADS = 256;

constexpr float H_SCALE = 512.0f;
constexpr float INV_H_SCALE = 1.0f / 512.0f;

// smem layout: [fp16 tile0][fp16 tile1][f32 stage][bank]
constexpr int PITCHB   = 144;                    // fp16 tile row pitch
constexpr int TILE_B   = 128 * PITCHB;           // 18432
constexpr int F32_PITCH = 72;                    // f32 per row (68 used + pad)
constexpr int F32_B    = 128 * F32_PITCH * 4;    // 36864
constexpr int BANK_TILES  = 86;
constexpr int BANK_B      = BANK_TILES * 256;    // 22016
constexpr int BANK_HALVES = BANK_TILES * 128;    // 11008
constexpr int F32_OFF  = 2 * TILE_B;             // 36864
constexpr int BANK_OFF = F32_OFF + F32_B;        // 73728
constexpr int SMEM_DYN = BANK_OFF + BANK_B;      // 95744 -> 2 CTAs/SM

// band: bank tile t nonzero iff t in [14, 67]
constexpr int TLO = 14, THI = 67;

// ====================== PTX helpers (family-agnostic, sm_80+) ======================
__device__ __forceinline__ u32 smem_u32(const void* p) {
    u32 a;
    asm("{ .reg .u64 t; cvta.to.shared.u64 t, %1; cvt.u32.u64 %0, t; }" : "=r"(a) : "l"(p));
    return a;
}
#define CP_ASYNC16(dst, src) \
    asm volatile("cp.async.cg.shared.global [%0], [%1], 16;" :: "r"(dst), "l"(src))
#define CP_COMMIT() asm volatile("cp.async.commit_group;" ::: "memory")
#define CP_WAIT0()  asm volatile("cp.async.wait_group 0;" ::: "memory")

#define LDSM4(r, addr) \
    asm volatile("ldmatrix.sync.aligned.m8n8.x4.shared.b16 {%0,%1,%2,%3}, [%4];" \
        : "=r"((r)[0]), "=r"((r)[1]), "=r"((r)[2]), "=r"((r)[3]) : "r"(addr))

#define MMA16816(d, a, b0, b1) \
    asm volatile("mma.sync.aligned.m16n8k16.row.col.f32.f16.f16.f32 " \
        "{%0,%1,%2,%3}, {%4,%5,%6,%7}, {%8,%9}, {%0,%1,%2,%3};" \
        : "+f"((d)[0]), "+f"((d)[1]), "+f"((d)[2]), "+f"((d)[3]) \
        : "r"((a)[0]), "r"((a)[1]), "r"((a)[2]), "r"((a)[3]), \
          "r"(b0), "r"(b1))

// ====================== reflect-limited extension ======================
__device__ __forceinline__ float xext_val(const float* __restrict__ xr, int e) {
    if (e < NE)         return 2.0f * xr[0]         - xr[NE - e];
    if (e < NE + T_LEN) return xr[e - NE];
    return 2.0f * xr[T_LEN - 1] - xr[2 * T_LEN - 2 + NE - e];
}

// ====================== per-chunk compute (identical to R10) ======================
template<int C, int WN>
__device__ __forceinline__ void compute_chunk(u32 abase, u32 bLane, const u32* aRel,
                                              float (&acc)[2][8][4]) {
    constexpr int B0 = (C - WN) * 8 + 8;
    if constexpr (B0 + 13 < TLO || B0 > THI) return;

    u32 bf[14][2];
    const u32 bb = bLane + (u32)(B0 * 256);
    #pragma unroll
    for (int p = 0; p < 7; p++) {
        if (B0 + 2 * p + 1 >= TLO && B0 + 2 * p <= THI) {
            u32 r4[4];
            LDSM4(r4, bb + p * 512);
            bf[2*p][0]   = r4[0]; bf[2*p][1]   = r4[1];
            bf[2*p+1][0] = r4[2]; bf[2*p+1][1] = r4[3];
        }
    }
    #pragma unroll
    for (int ks = 0; ks < 4; ks++) {
        if (B0 + 2 * ks + 7 >= TLO && B0 + 2 * ks <= THI) {
            u32 a[2][4];
            #pragma unroll
            for (int i = 0; i < 2; i++)
                LDSM4(a[i], abase + aRel[i] + ks * 32);
            #pragma unroll
            for (int i = 0; i < 2; i++)
                #pragma unroll
                for (int j = 0; j < 8; j++) {
                    const int t = B0 + 2 * ks - j + 7;
                    if (t >= TLO && t <= THI)
                        MMA16816(acc[i][j], a[i], bf[2*ks - j + 7][0], bf[2*ks - j + 7][1]);
                }
        }
    }
}

// ====================== fused kernel ======================
__global__ void __launch_bounds__(THREADS, 2)
fir_fused_kernel(const float* __restrict__ x, const float* __restrict__ h,
                 float* __restrict__ out) {
    extern __shared__ __align__(1024) char smem[];
    const int tid = threadIdx.x;
    const int wid = tid >> 5;
    const int lid = tid & 31;
    const int wm  = wid & 3;        // row slice of 32
    const int wn  = wid >> 2;       // t slice of 64
    const int t0    = blockIdx.x * NTT;
    const int rbase = blockIdx.y * MT;

    const u32 sb = smem_u32(smem);

    // ---- build diagonal bank in smem from h (one-time) ----
    {
        __half* bank = reinterpret_cast<__half*>(smem + BANK_OFF);
        for (int i = tid; i < BANK_HALVES; i += THREADS) {
            int t  = i >> 7;
            int r  = (i >> 3) & 15;
            int kk = i & 7;
            int np = r & 7;
            int kp = kk + ((r >= 8) ? 8 : 0);
            int j  = (8 * t - 120) + kp - np;
            float v = (j >= 0 && j < NT) ? h[NT - 1 - j] * H_SCALE : 0.0f;
            bank[i] = __float2half(v);
        }
    }

    // ---- f32 staging: chunk c covers x idx [base, base+68), base = t0+64c-208 ----
    const int r2   = tid >> 1;            // row handled by this thread (2 thr/row)
    const int half_ = tid & 1;
    const float* xrow2 = x + (size_t)(rbase + r2) * T_LEN;
    auto stageF = [&](int c) {
        const int base = t0 + c * KC - 208;
        const u32 drow = sb + F32_OFF + r2 * (F32_PITCH * 4);
        #pragma unroll
        for (int ss = 0; ss < 9; ss++) {
            int seg = half_ * 9 + ss;          // 0..16
            if (seg < 17) {
                int sidx = base + seg * 4;
                sidx = min(max(sidx, 0), T_LEN - 4);   // clamp (mult of 4 preserved)
                CP_ASYNC16(drow + seg * 16, (const char*)(xrow2 + sidx));
            }
        }
    };

    // ---- convert f32 stage -> fp16 tile s (RN, identical to old prep) ----
    auto convert = [&](int c, int s) {
        const float* f32b = reinterpret_cast<const float*>(smem + F32_OFF);
        char* tile = smem + s * TILE_B;
        #pragma unroll
        for (int it = 0; it < 4; it++) {
            int idx = it * THREADS + tid;      // 0..1023
            int r   = idx >> 3;
            int seg = idx & 7;
            const int m0 = t0 + c * KC + seg * 8 - 206;   // x index of first elem
            float v[8];
            if (m0 >= 2 && m0 + 9 < T_LEN) {
                // interior: staged segs fully valid (incl. alignment slop)
                const float* fb = f32b + r * F32_PITCH + 2 + seg * 8;
                #pragma unroll
                for (int q = 0; q < 8; q++) v[q] = fb[q];
            } else {
                const float* xr = x + (size_t)(rbase + r) * T_LEN;
                #pragma unroll
                for (int q = 0; q < 8; q++) {
                    int u = m0 + q + 206;      // xe index
                    v[q] = (u < S_LEN) ? xext_val(xr, u + OFF) : 0.0f;
                }
            }
            __half2 p[4];
            #pragma unroll
            for (int q = 0; q < 4; q++)
                p[q] = __floats2half2_rn(v[2*q], v[2*q + 1]);
            *reinterpret_cast<uint4*>(tile + r * PITCHB + seg * 16) =
                *reinterpret_cast<const uint4*>(p);
        }
    };

    // ---- ldmatrix bases ----
    u32 aRel[2];
    #pragma unroll
    for (int i = 0; i < 2; i++)
        aRel[i] = (wm * 32 + i * 16 + (lid & 15)) * PITCHB + ((lid >> 4) * 16);
    const u32 bLane = sb + BANK_OFF + lid * 16;

    float acc[2][8][4];
    #pragma unroll
    for (int i = 0; i < 2; i++)
        #pragma unroll
        for (int j = 0; j < 8; j++)
            #pragma unroll
            for (int q = 0; q < 4; q++) acc[i][j][q] = 0.0f;

    // ---- prologue ----
    stageF(0); CP_COMMIT();
    CP_WAIT0();
    __syncthreads();               // f32 stage + bank visible
    convert(0, 0);
    __syncthreads();               // tile0 visible; f32 buf reads done
    stageF(1); CP_COMMIT();

    // ---- main loop: compute(c) overlaps cp.async(c+1); then convert(c+1) ----
#define GSTEP(C)                                                                  \
    do {                                                                          \
        const u32 abase_ = sb + ((C) & 1) * TILE_B;                               \
        if (wn == 0) compute_chunk<(C), 0>(abase_, bLane, aRel, acc);             \
        else         compute_chunk<(C), 1>(abase_, bLane, aRel, acc);             \
        if ((C) + 1 < NCHUNK) {                                                   \
            CP_WAIT0();                                                           \
            __syncthreads();   /* f32(C+1) ready; tile (C+1)&1 readers done */    \
            convert((C) + 1, ((C) + 1) & 1);                                      \
            __syncthreads();   /* tile (C+1) visible; f32 buf free */             \
            if ((C) + 2 < NCHUNK) { stageF((C) + 2); CP_COMMIT(); }               \
        }                                                                         \
    } while (0)

    GSTEP(0); GSTEP(1); GSTEP(2); GSTEP(3); GSTEP(4);
    GSTEP(5); GSTEP(6); GSTEP(7); GSTEP(8);
#undef GSTEP

    // ---- epilogue ----
    #pragma unroll
    for (int i = 0; i < 2; i++) {
        int r0 = rbase + wm * 32 + i * 16 + (lid >> 2);
        #pragma unroll
        for (int j = 0; j < 8; j++) {
            int t = t0 + wn * 64 + j * 8 + 2 * (lid & 3);
            if (t < T_LEN) {
                *reinterpret_cast<float2*>(out + (size_t)r0 * T_LEN + t) =
                    make_float2(acc[i][j][0] * INV_H_SCALE, acc[i][j][1] * INV_H_SCALE);
                *reinterpret_cast<float2*>(out + (size_t)(r0 + 8) * T_LEN + t) =
                    make_float2(acc[i][j][2] * INV_H_SCALE, acc[i][j][3] * INV_H_SCALE);
            }
        }
    }
}

// ====================== launch ======================
extern "C" void kernel_launch(void* const* d_in, const int* in_sizes, int n_in,
                              void* d_out, int out_size)
{
    const float* x = (const float*)d_in[0];   // [64, 64, 4000] f32
    const float* h = (const float*)d_in[1];   // [413] f32
    float* out = (float*)d_out;

    cudaFuncSetAttribute(fir_fused_kernel,
                         cudaFuncAttributeMaxDynamicSharedMemorySize, SMEM_DYN);

    fir_fused_kernel<<<dim3(N_TTILE, N_RBLK), THREADS, SMEM_DYN>>>(x, h, out);
}

// round 13
// speedup vs baseline: 1.8163x; 1.8163x over previous
#include <cuda_runtime.h>
#include <cuda_fp16.h>
#include <cstdint>

typedef uint32_t u32;

// ====================== problem constants ======================
constexpr int T_LEN = 4000;
constexpr int NT    = 413;
constexpr int NE    = 412;
constexpr int OFF   = 206;              // xe[u] = x_ext[u + 206]
constexpr int S_LEN = T_LEN + NT;       // 4413
constexpr int NROWS = 4096;

constexpr int KC    = 64;               // sub-chunk (ldmatrix tile width)
constexpr int NSUB  = 9;                // sub-chunks 0..8 (K = 576)
constexpr int XE_W  = T_LEN + 576;      // 4576
constexpr int MT    = 128;              // rows per CTA
constexpr int NTT   = 128;              // t per CTA
constexpr int N_TTILE = (T_LEN + NTT - 1) / NTT;  // 32
constexpr int N_RBLK  = NROWS / MT;               // 32
constexpr int THREADS = 256;

constexpr float H_SCALE = 512.0f;
constexpr float INV_H_SCALE = 1.0f / 512.0f;

// smem: 2 big stages of 2 sub-tiles (128 rows x 64 fp16, pitch 144B) + bank
constexpr int PITCHB   = 144;
constexpr int TILE_B   = 128 * PITCHB;          // 18432
constexpr int STAGE_B  = 2 * TILE_B;            // 36864 (one big chunk = 128 k)
constexpr int BANK_TILES  = 86;
constexpr int BANK_B      = BANK_TILES * 256;   // 22016
constexpr int BANK_HALVES = BANK_TILES * 128;   // 11008
constexpr int BANK_OFF = 2 * STAGE_B;           // 73728
constexpr int SMEM_DYN = BANK_OFF + BANK_B;     // 95744 -> 2 CTAs/SM

// band: bank tile t nonzero iff t in [14, 67]
constexpr int TLO = 14, THI = 67;

// ====================== device scratch ======================
__device__ __align__(16) __half g_xe[(size_t)NROWS * XE_W];

// ====================== PTX helpers (family-agnostic, sm_80+) ======================
__device__ __forceinline__ u32 smem_u32(const void* p) {
    u32 a;
    asm("{ .reg .u64 t; cvta.to.shared.u64 t, %1; cvt.u32.u64 %0, t; }" : "=r"(a) : "l"(p));
    return a;
}
#define CP_ASYNC16(dst, src) \
    asm volatile("cp.async.cg.shared.global [%0], [%1], 16;" :: "r"(dst), "l"(src))
#define CP_COMMIT() asm volatile("cp.async.commit_group;" ::: "memory")
#define CP_WAIT0()  asm volatile("cp.async.wait_group 0;" ::: "memory")

#define LDSM4(r, addr) \
    asm volatile("ldmatrix.sync.aligned.m8n8.x4.shared.b16 {%0,%1,%2,%3}, [%4];" \
        : "=r"((r)[0]), "=r"((r)[1]), "=r"((r)[2]), "=r"((r)[3]) : "r"(addr))

#define MMA16816(d, a, b0, b1) \
    asm volatile("mma.sync.aligned.m16n8k16.row.col.f32.f16.f16.f32 " \
        "{%0,%1,%2,%3}, {%4,%5,%6,%7}, {%8,%9}, {%0,%1,%2,%3};" \
        : "+f"((d)[0]), "+f"((d)[1]), "+f"((d)[2]), "+f"((d)[3]) \
        : "r"((a)[0]), "r"((a)[1]), "r"((a)[2]), "r"((a)[3]), \
          "r"(b0), "r"(b1))

// ====================== prep kernel (xe only) ======================
__device__ __forceinline__ float xext_val(const float* __restrict__ xr, int e) {
    if (e < NE)         return 2.0f * xr[0]         - xr[NE - e];
    if (e < NE + T_LEN) return xr[e - NE];
    return 2.0f * xr[T_LEN - 1] - xr[2 * T_LEN - 2 + NE - e];
}

__global__ void prep_kernel(const float* __restrict__ x) {
    const int b = blockIdx.x;
    const float* xr = x + (size_t)b * T_LEN;
    __half* dst = g_xe + (size_t)b * XE_W;
    for (int seg = threadIdx.x; seg < XE_W / 8; seg += blockDim.x) {
        const int u0 = seg * 8;
        __half hv[8];
        #pragma unroll
        for (int q = 0; q < 8; q++) {
            int u = u0 + q;
            float v = (u < S_LEN) ? xext_val(xr, u + OFF) : 0.0f;
            hv[q] = __float2half(v);
        }
        *reinterpret_cast<uint4*>(dst + u0) = *reinterpret_cast<const uint4*>(hv);
    }
}

// ====================== per-sub-chunk compute (identical to R10) ======================
template<int C, int WN>
__device__ __forceinline__ void compute_chunk(u32 abase, u32 bLane, const u32* aRel,
                                              float (&acc)[2][8][4]) {
    constexpr int B0 = (C - WN) * 8 + 8;
    if constexpr (B0 + 13 < TLO || B0 > THI) return;

    u32 bf[14][2];
    const u32 bb = bLane + (u32)(B0 * 256);
    #pragma unroll
    for (int p = 0; p < 7; p++) {
        if (B0 + 2 * p + 1 >= TLO && B0 + 2 * p <= THI) {
            u32 r4[4];
            LDSM4(r4, bb + p * 512);
            bf[2*p][0]   = r4[0]; bf[2*p][1]   = r4[1];
            bf[2*p+1][0] = r4[2]; bf[2*p+1][1] = r4[3];
        }
    }
    #pragma unroll
    for (int ks = 0; ks < 4; ks++) {
        if (B0 + 2 * ks + 7 >= TLO && B0 + 2 * ks <= THI) {
            u32 a[2][4];
            #pragma unroll
            for (int i = 0; i < 2; i++)
                LDSM4(a[i], abase + aRel[i] + ks * 32);
            #pragma unroll
            for (int i = 0; i < 2; i++)
                #pragma unroll
                for (int j = 0; j < 8; j++) {
                    const int t = B0 + 2 * ks - j + 7;
                    if (t >= TLO && t <= THI)
                        MMA16816(acc[i][j], a[i], bf[2*ks - j + 7][0], bf[2*ks - j + 7][1]);
                }
        }
    }
}

// ====================== GEMM kernel ======================
__global__ void __launch_bounds__(THREADS, 2)
fir_gemm_kernel(const float* __restrict__ h, float* __restrict__ out) {
    extern __shared__ __align__(1024) char smem[];
    const int tid = threadIdx.x;
    const int wid = tid >> 5;
    const int lid = tid & 31;
    const int wm  = wid & 3;        // row slice of 32
    const int wn  = wid >> 2;       // t slice of 64
    const int t0    = blockIdx.x * NTT;
    const int rbase = blockIdx.y * MT;

    const u32 sb = smem_u32(smem);

    // ---- build diagonal bank in smem from h (one-time; validated in R12) ----
    {
        __half* bank = reinterpret_cast<__half*>(smem + BANK_OFF);
        for (int i = tid; i < BANK_HALVES; i += THREADS) {
            int t  = i >> 7;
            int r  = (i >> 3) & 15;
            int kk = i & 7;
            int np = r & 7;
            int kp = kk + ((r >= 8) ? 8 : 0);
            int j  = (8 * t - 120) + kp - np;
            float v = (j >= 0 && j < NT) ? h[NT - 1 - j] * H_SCALE : 0.0f;
            bank[i] = __float2half(v);
        }
    }

    // ---- A staging addresses (4 x 16B per thread per 64-k sub-chunk) ----
    const char* xebase = (const char*)g_xe;
    u32 asrc[4], adst[4];
    #pragma unroll
    for (int it = 0; it < 4; it++) {
        int idx = it * THREADS + tid;   // 0..1023
        int r = idx >> 3, seg = idx & 7;
        asrc[it] = (u32)(((size_t)(rbase + r) * XE_W + t0 + seg * 8) * 2);
        adst[it] = r * PITCHB + seg * 16;
    }
    // stage one 64-k sub-chunk c into dbase
    auto stageSub = [&](int c, u32 dbase) {
        const int koff = c * 128;
        #pragma unroll
        for (int it = 0; it < 4; it++)
            CP_ASYNC16(dbase + adst[it], xebase + asrc[it] + koff);
    };
    // stage big chunk bc = sub-chunks (2bc, 2bc+1) into stage buffer b
    auto stageBig = [&](int bc, int b) {
        stageSub(2 * bc,     sb + b * STAGE_B);
        stageSub(2 * bc + 1, sb + b * STAGE_B + TILE_B);
    };

    // ---- ldmatrix bases ----
    u32 aRel[2];
    #pragma unroll
    for (int i = 0; i < 2; i++)
        aRel[i] = (wm * 32 + i * 16 + (lid & 15)) * PITCHB + ((lid >> 4) * 16);
    const u32 bLane = sb + BANK_OFF + lid * 16;

    float acc[2][8][4];
    #pragma unroll
    for (int i = 0; i < 2; i++)
        #pragma unroll
        for (int j = 0; j < 8; j++)
            #pragma unroll
            for (int q = 0; q < 4; q++) acc[i][j][q] = 0.0f;

    // ---- prologue: stage big-chunk 0 (bank STS covered by first barrier) ----
    stageBig(0, 0);
    CP_COMMIT();

    // ---- 4 big chunks + 1 tail sub-chunk: 5 waits/barriers total ----
#define GBIG(BC)                                                                       \
    do {                                                                               \
        CP_WAIT0();                                                                    \
        __syncthreads();  /* big-chunk BC visible; prev buffer's readers done */       \
        if ((BC) < 3)      { stageBig((BC) + 1, ((BC) + 1) & 1); CP_COMMIT(); }        \
        else if ((BC) == 3) { stageSub(8, sb + 0 * STAGE_B);      CP_COMMIT(); }       \
        const u32 base_ = sb + ((BC) & 1) * STAGE_B;                                   \
        if (wn == 0) {                                                                 \
            compute_chunk<2*(BC),   0>(base_,          bLane, aRel, acc);              \
            compute_chunk<2*(BC)+1, 0>(base_ + TILE_B, bLane, aRel, acc);              \
        } else {                                                                       \
            compute_chunk<2*(BC),   1>(base_,          bLane, aRel, acc);              \
            compute_chunk<2*(BC)+1, 1>(base_ + TILE_B, bLane, aRel, acc);              \
        }                                                                              \
    } while (0)

    GBIG(0); GBIG(1); GBIG(2); GBIG(3);
#undef GBIG

    // tail: sub-chunk 8 (dead for wn=0 at compile time)
    CP_WAIT0();
    __syncthreads();
    if (wn == 0) compute_chunk<8, 0>(sb, bLane, aRel, acc);
    else         compute_chunk<8, 1>(sb, bLane, aRel, acc);

    // ---- epilogue ----
    #pragma unroll
    for (int i = 0; i < 2; i++) {
        int r0 = rbase + wm * 32 + i * 16 + (lid >> 2);
        #pragma unroll
        for (int j = 0; j < 8; j++) {
            int t = t0 + wn * 64 + j * 8 + 2 * (lid & 3);
            if (t < T_LEN) {
                *reinterpret_cast<float2*>(out + (size_t)r0 * T_LEN + t) =
                    make_float2(acc[i][j][0] * INV_H_SCALE, acc[i][j][1] * INV_H_SCALE);
                *reinterpret_cast<float2*>(out + (size_t)(r0 + 8) * T_LEN + t) =
                    make_float2(acc[i][j][2] * INV_H_SCALE, acc[i][j][3] * INV_H_SCALE);
            }
        }
    }
}

// ====================== launch ======================
extern "C" void kernel_launch(void* const* d_in, const int* in_sizes, int n_in,
                              void* d_out, int out_size)
{
    const float* x = (const float*)d_in[0];   // [64, 64, 4000] f32
    const float* h = (const float*)d_in[1];   // [413] f32
    float* out = (float*)d_out;

    cudaFuncSetAttribute(fir_gemm_kernel,
                         cudaFuncAttributeMaxDynamicSharedMemorySize, SMEM_DYN);

    prep_kernel<<<NROWS, 256>>>(x);
    fir_gemm_kernel<<<dim3(N_TTILE, N_RBLK), THREADS, SMEM_DYN>>>(h, out);
}

// round 14
// speedup vs baseline: 2.0113x; 1.1074x over previous
#include <cuda_runtime.h>
#include <cuda_fp16.h>
#include <cstdint>

typedef uint32_t u32;

// ====================== problem constants ======================
constexpr int T_LEN = 4000;
constexpr int NT    = 413;
constexpr int NE    = 412;
constexpr int OFF   = 206;              // xe[u] = x_ext[u + 206]
constexpr int S_LEN = T_LEN + NT;       // 4413
constexpr int NROWS = 4096;

constexpr int KC    = 64;               // K chunk
constexpr int NCHUNK = 9;
constexpr int XE_W  = T_LEN + 576;      // 4576
constexpr int MT    = 128;              // GEMM M (rows r)
constexpr int NTT   = 128;              // GEMM N (t positions)
constexpr int N_TTILE = (T_LEN + NTT - 1) / NTT;  // 32
constexpr int N_RBLK  = NROWS / MT;               // 32
constexpr int THREADS = 256;

constexpr float H_SCALE = 512.0f;
constexpr float INV_H_SCALE = 1.0f / 512.0f;

// A staging: 128 rows x 64 fp16, pitch 144B, 3 stages (R10-validated).
constexpr int PITCHB   = 144;
constexpr int STAGE_A  = 128 * PITCHB;          // 18432
constexpr int NSTAGE   = 3;
// Diagonal bank: B tile for diagonal d0 = 8t - 120, t in [0,86). 256B/tile.
constexpr int BANK_TILES  = 86;
constexpr int BANK_BYTES  = BANK_TILES * 256;   // 22016
constexpr int BANK_HALVES = BANK_TILES * 128;
constexpr int SMEM_DYN  = NSTAGE * STAGE_A + BANK_BYTES;   // 77312

// band: bank tile t nonzero iff t in [14, 67]
constexpr int TLO = 14, THI = 67;

// ====================== device scratch ======================
__device__ __align__(16) __half g_xe[(size_t)NROWS * XE_W];
__device__ __align__(16) __half g_Bd[BANK_HALVES];

// ====================== PTX helpers (family-agnostic, sm_80+) ======================
__device__ __forceinline__ u32 smem_u32(const void* p) {
    u32 a;
    asm("{ .reg .u64 t; cvta.to.shared.u64 t, %1; cvt.u32.u64 %0, t; }" : "=r"(a) : "l"(p));
    return a;
}
#define CP_ASYNC16(dst, src) \
    asm volatile("cp.async.cg.shared.global [%0], [%1], 16;" :: "r"(dst), "l"(src))
#define CP_COMMIT() asm volatile("cp.async.commit_group;" ::: "memory")

#define LDSM4(r, addr) \
    asm volatile("ldmatrix.sync.aligned.m8n8.x4.shared.b16 {%0,%1,%2,%3}, [%4];" \
        : "=r"((r)[0]), "=r"((r)[1]), "=r"((r)[2]), "=r"((r)[3]) : "r"(addr))

#define MMA16816(d, a, b0, b1) \
    asm volatile("mma.sync.aligned.m16n8k16.row.col.f32.f16.f16.f32 " \
        "{%0,%1,%2,%3}, {%4,%5,%6,%7}, {%8,%9}, {%0,%1,%2,%3};" \
        : "+f"((d)[0]), "+f"((d)[1]), "+f"((d)[2]), "+f"((d)[3]) \
        : "r"((a)[0]), "r"((a)[1]), "r"((a)[2]), "r"((a)[3]), \
          "r"(b0), "r"(b1))

// ====================== fused prep kernel (R10) ======================
__device__ __forceinline__ float xext_val(const float* __restrict__ xr, int e) {
    if (e < NE)         return 2.0f * xr[0]         - xr[NE - e];
    if (e < NE + T_LEN) return xr[e - NE];
    return 2.0f * xr[T_LEN - 1] - xr[2 * T_LEN - 2 + NE - e];
}

__global__ void prep_kernel(const float* __restrict__ x, const float* __restrict__ h) {
    const int b = blockIdx.x;
    if (b < NROWS) {
        const float* xr = x + (size_t)b * T_LEN;
        __half* dst = g_xe + (size_t)b * XE_W;
        for (int seg = threadIdx.x; seg < XE_W / 8; seg += blockDim.x) {
            const int u0 = seg * 8;
            __half hv[8];
            #pragma unroll
            for (int q = 0; q < 8; q++) {
                int u = u0 + q;
                float v = (u < S_LEN) ? xext_val(xr, u + OFF) : 0.0f;
                hv[q] = __float2half(v);
            }
            *reinterpret_cast<uint4*>(dst + u0) = *reinterpret_cast<const uint4*>(hv);
        }
    } else {
        int idx = (b - NROWS) * blockDim.x + threadIdx.x;
        if (idx < BANK_HALVES) {
            int t  = idx >> 7;
            int r  = (idx >> 3) & 15;
            int kk = idx & 7;
            int np = r & 7;
            int kp = kk + ((r >= 8) ? 8 : 0);
            int j  = (8 * t - 120) + kp - np;       // hrev index
            float v = (j >= 0 && j < NT) ? h[NT - 1 - j] * H_SCALE : 0.0f;
            g_Bd[idx] = __float2half(v);
        }
    }
}
constexpr int PREP_BANK_BLOCKS = (BANK_HALVES + 255) / 256;   // 43

// ====================== per-chunk compute, rolling B window ======================
// bf ring: pair-index (tile>>1) & 7 -> 4 regs (tiles 2p and 2p+1).
// Live chunks have B0 = 8..64; first live chunk (B0==8) does a full in-band load,
// later chunks load only the 4 new pairs (tiles >= B0+6). Window <= 7 pairs,
// consecutive, so ring indices are collision-free.
template<int C, int WN>
__device__ __forceinline__ void compute_chunk(u32 abase, u32 bLane, const u32* aRel,
                                              float (&acc)[2][8][4], u32 (&bf)[8][4]) {
    constexpr int B0 = (C - WN) * 8 + 8;
    if constexpr (B0 + 13 < TLO || B0 > THI) return;   // dead chunk
    constexpr bool FIRST = (B0 == 8);

    #pragma unroll
    for (int p = 0; p < 7; p++) {
        const int tg = B0 + 2 * p;                     // pair covers tiles (tg, tg+1)
        const bool inband = (tg + 1 >= TLO) && (tg <= THI);
        const bool isnew  = FIRST || (tg >= B0 + 6);   // not covered by prev window
        if (inband && isnew)
            LDSM4(bf[(tg >> 1) & 7], bLane + (u32)(tg * 256));
    }
    #pragma unroll
    for (int ks = 0; ks < 4; ks++) {
        if (B0 + 2 * ks + 7 >= TLO && B0 + 2 * ks <= THI) {
            u32 a[2][4];
            #pragma unroll
            for (int i = 0; i < 2; i++)
                LDSM4(a[i], abase + aRel[i] + ks * 32);
            #pragma unroll
            for (int i = 0; i < 2; i++)
                #pragma unroll
                for (int j = 0; j < 8; j++) {
                    const int t = B0 + 2 * ks - j + 7;
                    if (t >= TLO && t <= THI) {
                        const int pr = (t >> 1) & 7, sel = (t & 1) * 2;
                        MMA16816(acc[i][j], a[i], bf[pr][sel], bf[pr][sel + 1]);
                    }
                }
        }
    }
}

// ====================== GEMM kernel (R10 pipeline) ======================
__global__ void __launch_bounds__(THREADS, 2)
fir_gemm_kernel(float* __restrict__ out) {
    extern __shared__ __align__(1024) char smem[];
    const int tid = threadIdx.x;
    const int wid = tid >> 5;
    const int lid = tid & 31;
    const int wm  = wid & 3;        // row slice of 32
    const int wn  = wid >> 2;       // t slice of 64
    const int t0    = blockIdx.x * NTT;
    const int rbase = blockIdx.y * MT;

    const u32 sb   = smem_u32(smem);
    const u32 bank = sb + NSTAGE * STAGE_A;

    // ---- A staging addresses (4 x 16B per thread per chunk) ----
    const char* xebase = (const char*)g_xe;
    u32 asrc[4], adst[4];
    #pragma unroll
    for (int it = 0; it < 4; it++) {
        int idx = it * THREADS + tid;   // 0..1023
        int r = idx >> 3, seg = idx & 7;
        asrc[it] = (u32)(((size_t)(rbase + r) * XE_W + t0 + seg * 8) * 2);
        adst[it] = r * PITCHB + seg * 16;
    }
    auto stageA = [&](int c, u32 dbase) {
        const int koff = c * 128;
        #pragma unroll
        for (int it = 0; it < 4; it++)
            CP_ASYNC16(dbase + adst[it], xebase + asrc[it] + koff);
    };

    // ---- one-time bank load + first two A stages ----
    {
        const char* bdbase = (const char*)g_Bd;
        for (int i = tid; i < BANK_BYTES / 16; i += THREADS)
            CP_ASYNC16(bank + i * 16, bdbase + (size_t)i * 16);
    }
    stageA(0, sb);
    CP_COMMIT();                          // group: bank + chunk0
    stageA(1, sb + STAGE_A);
    CP_COMMIT();                          // group: chunk1

    // ---- ldmatrix bases ----
    u32 aRel[2];
    #pragma unroll
    for (int i = 0; i < 2; i++)
        aRel[i] = (wm * 32 + i * 16 + (lid & 15)) * PITCHB + ((lid >> 4) * 16);
    const u32 bLane = bank + lid * 16;

    float acc[2][8][4];
    #pragma unroll
    for (int i = 0; i < 2; i++)
        #pragma unroll
        for (int j = 0; j < 8; j++)
            #pragma unroll
            for (int q = 0; q < 4; q++) acc[i][j][q] = 0.0f;

    u32 bf[8][4];     // rolling B-fragment ring (persists across chunks)

#define GSTEP(C)                                                                         \
    do {                                                                                 \
        if ((C) == NCHUNK - 1) asm volatile("cp.async.wait_group 0;" ::: "memory");      \
        else                   asm volatile("cp.async.wait_group 1;" ::: "memory");      \
        __syncthreads();                                                                 \
        if ((C) + 2 < NCHUNK) {                                                          \
            stageA((C) + 2, sb + (((C) + 2) % NSTAGE) * STAGE_A);                        \
            CP_COMMIT();                                                                 \
        }                                                                                \
        const u32 abase_ = sb + ((C) % NSTAGE) * STAGE_A;                                \
        if (wn == 0) compute_chunk<(C), 0>(abase_, bLane, aRel, acc, bf);                \
        else         compute_chunk<(C), 1>(abase_, bLane, aRel, acc, bf);                \
    } while (0)

    GSTEP(0); GSTEP(1); GSTEP(2); GSTEP(3); GSTEP(4);
    GSTEP(5); GSTEP(6); GSTEP(7); GSTEP(8);
#undef GSTEP

    // ---- epilogue: D[m=r][n=t] -> out[r*T_LEN + t], undo H_SCALE ----
    #pragma unroll
    for (int i = 0; i < 2; i++) {
        int r0 = rbase + wm * 32 + i * 16 + (lid >> 2);
        #pragma unroll
        for (int j = 0; j < 8; j++) {
            int t = t0 + wn * 64 + j * 8 + 2 * (lid & 3);
            if (t < T_LEN) {
                *reinterpret_cast<float2*>(out + (size_t)r0 * T_LEN + t) =
                    make_float2(acc[i][j][0] * INV_H_SCALE, acc[i][j][1] * INV_H_SCALE);
                *reinterpret_cast<float2*>(out + (size_t)(r0 + 8) * T_LEN + t) =
                    make_float2(acc[i][j][2] * INV_H_SCALE, acc[i][j][3] * INV_H_SCALE);
            }
        }
    }
}

// ====================== launch ======================
extern "C" void kernel_launch(void* const* d_in, const int* in_sizes, int n_in,
                              void* d_out, int out_size)
{
    const float* x = (const float*)d_in[0];   // [64, 64, 4000] f32
    const float* h = (const float*)d_in[1];   // [413] f32
    float* out = (float*)d_out;

    cudaFuncSetAttribute(fir_gemm_kernel,
                         cudaFuncAttributeMaxDynamicSharedMemorySize, SMEM_DYN);

    prep_kernel<<<NROWS + PREP_BANK_BLOCKS, 256>>>(x, h);
    fir_gemm_kernel<<<dim3(N_TTILE, N_RBLK), THREADS, SMEM_DYN>>>(out);
}